// round 4
// baseline (speedup 1.0000x reference)
#include <cuda_runtime.h>

#define BATCH 32
#define H 512
#define W 512
#define NSTEPS 10
#define NPIX (H * W)

// Ping-pong scratch (allocation-free rule: __device__ globals).
__device__ float g_buf0[BATCH * NPIX];
__device__ float g_buf1[BATCH * NPIX];
__device__ int   g_t[BATCH];

// Normalize t into g_t as int32. The jax reference declares int64, but under
// default jax config it may materialize as int32. Detect: if the buffer is
// int64 (little-endian, values in [0,10)), every odd 32-bit word of the first
// 32 words is a zero high-half. Only the first 128 bytes are inspected for
// the decision (safe under either dtype); the 64-word read happens only when
// int64 was detected (buffer is then genuinely 256B).
__global__ void prep_t_kernel(const int* __restrict__ traw) {
    int lane = threadIdx.x;  // 0..31
    int w = traw[lane];
    unsigned oddnz = __ballot_sync(0xffffffffu, ((lane & 1) != 0) && (w != 0));
    int v = (oddnz == 0u) ? traw[2 * lane] : w;
    v = min(max(v, 0), NSTEPS);
    g_t[lane] = v;
}

__device__ __forceinline__ void sort3(float a, float b, float c,
                                      float& lo, float& md, float& hi) {
    float s = fminf(a, b);
    float t = fmaxf(a, b);
    lo = fminf(s, c);
    hi = fmaxf(t, c);
    md = fmaxf(s, fminf(t, c));
}

__device__ __forceinline__ float med3(float a, float b, float c) {
    return fmaxf(fminf(a, b), fminf(fmaxf(a, b), c));
}

// Load one input row segment (cols x4-1 .. x4+4, clamped) and produce the
// sorted horizontal triples for output columns x4..x4+3.
__device__ __forceinline__ void load_row(const float* __restrict__ rowp, int x4,
                                         float lo[4], float md[4], float hi[4]) {
    float4 c = *reinterpret_cast<const float4*>(rowp + x4);
    float lft = rowp[(x4 == 0) ? 0 : (x4 - 1)];
    float rgt = rowp[(x4 + 4 >= W) ? (W - 1) : (x4 + 4)];
    float v0 = lft, v1 = c.x, v2 = c.y, v3 = c.z, v4 = c.w, v5 = rgt;
    sort3(v0, v1, v2, lo[0], md[0], hi[0]);
    sort3(v1, v2, v3, lo[1], md[1], hi[1]);
    sort3(v2, v3, v4, lo[2], md[2], hi[2]);
    sort3(v3, v4, v5, lo[3], md[3], hi[3]);
}

// One blur iteration j. Each thread: 4-wide (float4) x 4-tall column.
// Block 32x8 threads -> 128x32 pixel tile. Grid (4, 16, 32).
__global__ void __launch_bounds__(256, 1) median_step_kernel(
    const float* __restrict__ x, float* __restrict__ out, int j) {
    int b = blockIdx.z;
    int tb = g_t[b];
    bool copy0 = (j == 0) && (tb == 0);
    if (j >= tb && !copy0) return;

    const float* src;
    float* dst;
    if (copy0) {
        src = x;
        dst = out;
    } else {
        src = (j == 0) ? x : (((j - 1) & 1) ? g_buf1 : g_buf0);
        // Last active iteration for this batch writes straight to out.
        dst = (j >= tb - 1) ? out : ((j & 1) ? g_buf1 : g_buf0);
    }
    const float* sb = src + (size_t)b * NPIX;
    float* db = dst + (size_t)b * NPIX;

    int x4 = (blockIdx.x * 32 + threadIdx.x) * 4;  // 0..508, 16B aligned
    int y0 = (blockIdx.y * 8 + threadIdx.y) * 4;   // 0..508

    if (copy0) {
#pragma unroll
        for (int r = 0; r < 4; r++) {
            *reinterpret_cast<float4*>(db + (y0 + r) * W + x4) =
                *reinterpret_cast<const float4*>(sb + (y0 + r) * W + x4);
        }
        return;
    }

    // Rolling sorted-row triples: slot s holds (min,med,max) of the horizontal
    // triples of one input row, for the 4 output columns.
    float lo[3][4], md[3][4], hi[3][4];

    {
        int rm = (y0 == 0) ? 0 : (y0 - 1);  // edge clamp (pad mode 'edge')
        load_row(sb + rm * W, x4, lo[0], md[0], hi[0]);
        load_row(sb + y0 * W, x4, lo[1], md[1], hi[1]);
    }

#pragma unroll
    for (int r = 0; r < 4; r++) {
        int yn = y0 + r + 1;
        if (yn > H - 1) yn = H - 1;  // edge clamp
        int ic = (r + 2) % 3;
        load_row(sb + yn * W, x4, lo[ic], md[ic], hi[ic]);

        int ia = r % 3, ib = (r + 1) % 3;
        float res[4];
#pragma unroll
        for (int k = 0; k < 4; k++) {
            // median9 = med3( max(mins), med3(meds), min(maxs) )
            float mn  = fmaxf(fmaxf(lo[ia][k], lo[ib][k]), lo[ic][k]);
            float mx  = fminf(fminf(hi[ia][k], hi[ib][k]), hi[ic][k]);
            float mdv = med3(md[ia][k], md[ib][k], md[ic][k]);
            res[k] = med3(mn, mdv, mx);
        }
        *reinterpret_cast<float4*>(db + (y0 + r) * W + x4) =
            make_float4(res[0], res[1], res[2], res[3]);
    }
}

extern "C" void kernel_launch(void* const* d_in, const int* in_sizes, int n_in,
                              void* d_out, int out_size) {
    const float* x = (const float*)d_in[0];
    const int* traw = (const int*)d_in[1];
    float* out = (float*)d_out;

    prep_t_kernel<<<1, 32>>>(traw);

    dim3 block(32, 8);
    dim3 grid(W / 128, H / 32, BATCH);
    for (int j = 0; j < NSTEPS; j++) {
        median_step_kernel<<<grid, block>>>(x, out, j);
    }
}